// round 1
// baseline (speedup 1.0000x reference)
#include <cuda_runtime.h>

#define GN 16
#define GQ 4096
#define GC 77
#define GD 512
#define GDC 768
#define GH 8
#define GS 64
#define GM (GN * GQ)  // 65536

// Scratch (device globals: allocation-free per harness rules)
__device__ float g_q[(size_t)GM * GD];        // 134 MB
__device__ float g_k[(size_t)GN * GC * GD];   // 2.5 MB
__device__ float g_v[(size_t)GN * GC * GD];   // 2.5 MB
__device__ float g_att[(size_t)GM * GD];      // 134 MB

// ---------------------------------------------------------------------------
// SGEMM: C[M,N] = A[M,K] * B[K,N] (+bias), all row-major.
// Requires N % 128 == 0, K % 8 == 0. M is bounds-guarded.
// 128x128 block tile, BK=8, 256 threads, 8x8 register microtile.
// ---------------------------------------------------------------------------
template <bool HAS_BIAS>
__global__ __launch_bounds__(256) void sgemm128(
    const float* __restrict__ A, const float* __restrict__ B,
    const float* __restrict__ bias, float* __restrict__ C,
    int M, int N, int K)
{
    __shared__ float As[8][128];  // transposed A tile: As[k][row]
    __shared__ float Bs[8][128];  // Bs[k][col]

    const int tid = threadIdx.x;
    const int rowBase = blockIdx.y * 128;
    const int colBase = blockIdx.x * 128;

    const int aRow = tid >> 1;           // 0..127
    const int aCol = (tid & 1) * 4;      // 0 or 4
    const int bRow = tid >> 5;           // 0..7
    const int bCol = (tid & 31) * 4;     // 0..124
    const int ty = tid >> 4;             // 0..15
    const int tx = tid & 15;             // 0..15

    float acc[8][8];
#pragma unroll
    for (int i = 0; i < 8; i++)
#pragma unroll
        for (int j = 0; j < 8; j++) acc[i][j] = 0.f;

    const bool aValid = (rowBase + aRow) < M;
    const float* Aptr = A + (size_t)(rowBase + aRow) * K + aCol;
    const float* Bptr = B + (size_t)bRow * N + colBase + bCol;

    for (int k0 = 0; k0 < K; k0 += 8) {
        float4 av = aValid ? *(const float4*)(Aptr + k0)
                           : make_float4(0.f, 0.f, 0.f, 0.f);
        float4 bv = *(const float4*)(Bptr + (size_t)k0 * N);
        As[aCol + 0][aRow] = av.x;
        As[aCol + 1][aRow] = av.y;
        As[aCol + 2][aRow] = av.z;
        As[aCol + 3][aRow] = av.w;
        *(float4*)&Bs[bRow][bCol] = bv;
        __syncthreads();

#pragma unroll
        for (int kk = 0; kk < 8; kk++) {
            float a[8], b[8];
#pragma unroll
            for (int i = 0; i < 8; i++) a[i] = As[kk][ty * 8 + i];
#pragma unroll
            for (int j = 0; j < 8; j++) b[j] = Bs[kk][tx * 8 + j];
#pragma unroll
            for (int i = 0; i < 8; i++)
#pragma unroll
                for (int j = 0; j < 8; j++)
                    acc[i][j] = fmaf(a[i], b[j], acc[i][j]);
        }
        __syncthreads();
    }

#pragma unroll
    for (int i = 0; i < 8; i++) {
        int r = rowBase + ty * 8 + i;
        if (r >= M) continue;
        float* Cp = C + (size_t)r * N + colBase + tx * 8;
        float outv[8];
#pragma unroll
        for (int j = 0; j < 8; j++) {
            outv[j] = acc[i][j];
            if (HAS_BIAS) outv[j] += bias[colBase + tx * 8 + j];
        }
        *(float4*)(Cp) = *(float4*)(outv);
        *(float4*)(Cp + 4) = *(float4*)(outv + 4);
    }
}

// ---------------------------------------------------------------------------
// Fused attention over precomputed q,k,v (layout [n][seq][h*64+s]).
// Block = 256 threads (8 warps); each block handles one (n, h) and 64 q-rows;
// each warp owns 8 q-rows. K/V tile (77x64) cached in smem, padded stride 65
// (odd => conflict-free column access). 1/sqrt(S) folded into q at load.
// ---------------------------------------------------------------------------
__global__ __launch_bounds__(256) void attn_kernel(
    const float* __restrict__ qg, const float* __restrict__ kg,
    const float* __restrict__ vg, float* __restrict__ og)
{
    extern __shared__ float sm[];
    float* ks = sm;                  // 77 * 65
    float* vs = ks + GC * 65;        // 77 * 65
    float* qs = vs + GC * 65;        // 64 * 64
    float* ws = qs + 64 * 64;        // 64 * 80

    const int n = blockIdx.z, h = blockIdx.y;
    const int qbase = blockIdx.x * 64;
    const int tid = threadIdx.x;
    const int warp = tid >> 5, lane = tid & 31;

    const float* kb = kg + (size_t)n * GC * GD + h * GS;
    const float* vb = vg + (size_t)n * GC * GD + h * GS;
    for (int i = tid; i < GC * GS; i += 256) {
        int c = i >> 6, s = i & 63;
        ks[c * 65 + s] = kb[(size_t)c * GD + s];
        vs[c * 65 + s] = vb[(size_t)c * GD + s];
    }
    const float* qb = qg + ((size_t)n * GQ + qbase) * GD + h * GS;
    for (int i = tid; i < 64 * 64; i += 256) {
        int r = i >> 6, s = i & 63;
        qs[i] = qb[(size_t)r * GD + s] * 0.125f;  // 1/sqrt(64)
    }
    __syncthreads();

    const int r0 = warp * 8;
    const bool c2ok = (lane < GC - 64);  // lane < 13

    // ---- scores: each lane owns c in {lane, lane+32, lane+64} for 8 rows
    float sc0[8], sc1[8], sc2[8];
#pragma unroll
    for (int r = 0; r < 8; r++) { sc0[r] = 0.f; sc1[r] = 0.f; sc2[r] = 0.f; }
#pragma unroll 4
    for (int s = 0; s < 64; s++) {
        float k0 = ks[lane * 65 + s];
        float k1 = ks[(lane + 32) * 65 + s];
        float k2 = c2ok ? ks[(lane + 64) * 65 + s] : 0.f;
#pragma unroll
        for (int r = 0; r < 8; r++) {
            float qv = qs[(r0 + r) * 64 + s];
            sc0[r] = fmaf(qv, k0, sc0[r]);
            sc1[r] = fmaf(qv, k1, sc1[r]);
            sc2[r] = fmaf(qv, k2, sc2[r]);
        }
    }

    // ---- softmax per row (warp-wide shuffle reduce over 77 scores)
#pragma unroll
    for (int r = 0; r < 8; r++) {
        float s2 = c2ok ? sc2[r] : -1e30f;
        float m = fmaxf(fmaxf(sc0[r], sc1[r]), s2);
#pragma unroll
        for (int o = 16; o; o >>= 1)
            m = fmaxf(m, __shfl_xor_sync(0xffffffffu, m, o));
        float e0 = __expf(sc0[r] - m);
        float e1 = __expf(sc1[r] - m);
        float e2 = c2ok ? __expf(s2 - m) : 0.f;
        float sum = e0 + e1 + e2;
#pragma unroll
        for (int o = 16; o; o >>= 1)
            sum += __shfl_xor_sync(0xffffffffu, sum, o);
        float inv = __frcp_rn(sum);
        ws[(r0 + r) * 80 + lane] = e0 * inv;
        ws[(r0 + r) * 80 + lane + 32] = e1 * inv;
        if (c2ok) ws[(r0 + r) * 80 + lane + 64] = e2 * inv;
    }
    __syncwarp();

    // ---- output: out[s] = sum_c w[c] * v[c][s]; lane owns s=lane, lane+32
    float a0[8], a1[8];
#pragma unroll
    for (int r = 0; r < 8; r++) { a0[r] = 0.f; a1[r] = 0.f; }
    for (int c = 0; c < GC; c++) {
        float v0 = vs[c * 65 + lane];
        float v1 = vs[c * 65 + lane + 32];
#pragma unroll
        for (int r = 0; r < 8; r++) {
            float w = ws[(r0 + r) * 80 + c];
            a0[r] = fmaf(w, v0, a0[r]);
            a1[r] = fmaf(w, v1, a1[r]);
        }
    }

    float* ob = og + ((size_t)n * GQ + qbase) * GD + h * GS;
#pragma unroll
    for (int r = 0; r < 8; r++) {
        ob[(size_t)(r0 + r) * GD + lane] = a0[r];
        ob[(size_t)(r0 + r) * GD + lane + 32] = a1[r];
    }
}

// ---------------------------------------------------------------------------
extern "C" void kernel_launch(void* const* d_in, const int* in_sizes, int n_in,
                              void* d_out, int out_size)
{
    const float* query   = (const float*)d_in[0];  // [16,4096,512]
    const float* context = (const float*)d_in[1];  // [16,77,768]
    const float* Wq      = (const float*)d_in[2];  // [512,512]
    const float* Wk      = (const float*)d_in[3];  // [768,512]
    const float* Wv      = (const float*)d_in[4];  // [768,512]
    const float* Wo      = (const float*)d_in[5];  // [512,512]
    const float* bo      = (const float*)d_in[6];  // [512]
    float* out = (float*)d_out;

    void *pq, *pk, *pv, *pa;
    cudaGetSymbolAddress(&pq, g_q);
    cudaGetSymbolAddress(&pk, g_k);
    cudaGetSymbolAddress(&pv, g_v);
    cudaGetSymbolAddress(&pa, g_att);

    // K/V projections: [1232,768] x [768,512]
    {
        dim3 grid(GD / 128, (GN * GC + 127) / 128);
        sgemm128<false><<<grid, 256>>>(context, Wk, nullptr, (float*)pk,
                                       GN * GC, GD, GDC);
        sgemm128<false><<<grid, 256>>>(context, Wv, nullptr, (float*)pv,
                                       GN * GC, GD, GDC);
    }
    // Q projection: [65536,512] x [512,512]
    {
        dim3 grid(GD / 128, GM / 128);
        sgemm128<false><<<grid, 256>>>(query, Wq, nullptr, (float*)pq,
                                       GM, GD, GD);
    }
    // Attention
    {
        int smem = (GC * 65 * 2 + 64 * 64 + 64 * 80) * (int)sizeof(float);
        cudaFuncSetAttribute(attn_kernel,
                             cudaFuncAttributeMaxDynamicSharedMemorySize, smem);
        dim3 grid(GQ / 64, GH, GN);
        attn_kernel<<<grid, 256, smem>>>((const float*)pq, (const float*)pk,
                                         (const float*)pv, (float*)pa);
    }
    // Output projection + bias: [65536,512] x [512,512]
    {
        dim3 grid(GD / 128, GM / 128);
        sgemm128<true><<<grid, 256>>>((const float*)pa, Wo, bo, out,
                                      GM, GD, GD);
    }
}

// round 4
// speedup vs baseline: 1.6985x; 1.6985x over previous
#include <cuda_runtime.h>
#include <cuda_bf16.h>
#include <cstdint>

#define GN 16
#define GQ 4096
#define GC 77
#define GD 512
#define GDC 768
#define GH 8
#define GS 64
#define GM (GN * GQ)  // 65536

// ---------------- scratch (device globals, allocation-free) ----------------
__device__ float g_q[(size_t)GM * GD];               // fp32 q after projection
__device__ float g_k[(size_t)GN * GC * GD];
__device__ float g_v[(size_t)GN * GC * GD];
__device__ __nv_bfloat16 g_qhi[(size_t)GM * GD];     // query hi/lo
__device__ __nv_bfloat16 g_qlo[(size_t)GM * GD];
__device__ __nv_bfloat16 g_ahi[(size_t)GM * GD];     // attn out hi/lo
__device__ __nv_bfloat16 g_alo[(size_t)GM * GD];
__device__ __nv_bfloat16 g_wqT_hi[GD * GD], g_wqT_lo[GD * GD];  // Wq^T [N][K]
__device__ __nv_bfloat16 g_woT_hi[GD * GD], g_woT_lo[GD * GD];  // Wo^T [N][K]

__device__ __forceinline__ uint32_t smem_u32(const void* p) {
    uint32_t a;
    asm("{ .reg .u64 t; cvta.to.shared.u64 t, %1; cvt.u32.u64 %0, t; }"
        : "=r"(a) : "l"(p));
    return a;
}
__device__ __forceinline__ void cp_async16(uint32_t dst, const void* src) {
    asm volatile("cp.async.cg.shared.global [%0], [%1], 16;"
                 :: "r"(dst), "l"(src) : "memory");
}
#define CP_COMMIT() asm volatile("cp.async.commit_group;" ::: "memory")

__device__ __forceinline__ void ldm_x4(uint32_t (&f)[4], uint32_t addr) {
    asm volatile("ldmatrix.sync.aligned.m8n8.x4.shared.b16 {%0,%1,%2,%3}, [%4];"
                 : "=r"(f[0]), "=r"(f[1]), "=r"(f[2]), "=r"(f[3]) : "r"(addr));
}
__device__ __forceinline__ void mma16816(float (&d)[4], const uint32_t (&a)[4],
                                         uint32_t b0, uint32_t b1) {
    asm volatile(
        "mma.sync.aligned.m16n8k16.row.col.f32.bf16.bf16.f32 "
        "{%0,%1,%2,%3}, {%4,%5,%6,%7}, {%8,%9}, {%0,%1,%2,%3};"
        : "+f"(d[0]), "+f"(d[1]), "+f"(d[2]), "+f"(d[3])
        : "r"(a[0]), "r"(a[1]), "r"(a[2]), "r"(a[3]), "r"(b0), "r"(b1));
}

__device__ __forceinline__ void split_bf16(float x, __nv_bfloat16& hi, __nv_bfloat16& lo) {
    hi = __float2bfloat16_rn(x);
    lo = __float2bfloat16_rn(x - __bfloat162float(hi));
}

// ---------------------------------------------------------------------------
// bf16x3 mma.sync GEMM: C = A*Bt^T (+bias), fp32-equivalent accuracy.
// A given as (Ahi, Alo), Bt as (Bhi, Blo); acc += ahi*bhi + ahi*blo + alo*bhi.
// 128x128 block, BK=32, 8 warps (4x2), warp tile 32x64, double-buffered.
// Smem rows padded to 40 bf16 (80B) => conflict-free ldmatrix.
// ---------------------------------------------------------------------------
#define LDT 40
#define TILE_B (128 * LDT)            // elems per single tile
#define TILE_BYTES (TILE_B * 2)       // 10240 B
#define STAGE_BYTES (4 * TILE_BYTES)  // Ahi, Alo, Bhi, Blo
#define GEMM_SMEM (2 * STAGE_BYTES)   // 81920 B

template <bool HAS_BIAS>
__global__ __launch_bounds__(256) void gemm_mma3(
    const __nv_bfloat16* __restrict__ Ahi, const __nv_bfloat16* __restrict__ Alo,
    const __nv_bfloat16* __restrict__ Bhi, const __nv_bfloat16* __restrict__ Blo,
    const float* __restrict__ bias, float* __restrict__ C,
    int M, int N, int K)
{
    extern __shared__ __align__(16) char gsm[];
    const uint32_t sa = smem_u32(gsm);

    const int tid = threadIdx.x;
    const int wid = tid >> 5, lane = tid & 31;
    const int warp_m = wid & 3;
    const int warp_n = wid >> 2;
    const int rowBase = blockIdx.y * 128;
    const int colBase = blockIdx.x * 128;

    const size_t aOff = (size_t)rowBase * K;
    const size_t bOff = (size_t)colBase * K;

    // per-thread load coords: 512 16B-chunks per tile, 2 per thread
    const int ldr0 = tid >> 2, ldc0 = (tid & 3);
    const int ldr1 = (tid + 256) >> 2, ldc1 = (tid & 3);

    const int q = lane >> 3, r = lane & 7;
    const int a_row = warp_m * 32 + ((q & 1) * 8) + r;
    const int a_kof = (q >> 1) * 8;
    const int b_row = warp_n * 64 + ((q >> 1) * 8) + r;
    const int b_kof = (q & 1) * 8;

    float acc[2][8][4];
#pragma unroll
    for (int i = 0; i < 2; i++)
#pragma unroll
        for (int j = 0; j < 8; j++)
#pragma unroll
            for (int t = 0; t < 4; t++) acc[i][j][t] = 0.f;

    const int NC = K >> 5;

    auto load_stage = [&](int c) {
        const int k0 = c << 5;
        const uint32_t st = sa + (c & 1) * STAGE_BYTES;
        const uint32_t o0 = (ldr0 * LDT + ldc0 * 8) * 2;
        const uint32_t o1 = (ldr1 * LDT + ldc1 * 8) * 2;
        const size_t g0 = (size_t)ldr0 * K + k0 + ldc0 * 8;
        const size_t g1 = (size_t)ldr1 * K + k0 + ldc1 * 8;
        cp_async16(st + 0 * TILE_BYTES + o0, Ahi + aOff + g0);
        cp_async16(st + 0 * TILE_BYTES + o1, Ahi + aOff + g1);
        cp_async16(st + 1 * TILE_BYTES + o0, Alo + aOff + g0);
        cp_async16(st + 1 * TILE_BYTES + o1, Alo + aOff + g1);
        cp_async16(st + 2 * TILE_BYTES + o0, Bhi + bOff + g0);
        cp_async16(st + 2 * TILE_BYTES + o1, Bhi + bOff + g1);
        cp_async16(st + 3 * TILE_BYTES + o0, Blo + bOff + g0);
        cp_async16(st + 3 * TILE_BYTES + o1, Blo + bOff + g1);
        CP_COMMIT();
    };

    load_stage(0);

    for (int c = 0; c < NC; c++) {
        if (c + 1 < NC) {
            load_stage(c + 1);
            asm volatile("cp.async.wait_group 1;" ::: "memory");
        } else {
            asm volatile("cp.async.wait_group 0;" ::: "memory");
        }
        __syncthreads();

        const uint32_t st = sa + (c & 1) * STAGE_BYTES;
#pragma unroll
        for (int ks = 0; ks < 2; ks++) {
            uint32_t afh[2][4], afl[2][4];
#pragma unroll
            for (int i = 0; i < 2; i++) {
                uint32_t ao = ((a_row + i * 16) * LDT + ks * 16 + a_kof) * 2;
                ldm_x4(afh[i], st + 0 * TILE_BYTES + ao);
                ldm_x4(afl[i], st + 1 * TILE_BYTES + ao);
            }
            uint32_t bfh[4][4], bfl[4][4];
#pragma unroll
            for (int ng = 0; ng < 4; ng++) {
                uint32_t bo = ((b_row + ng * 16) * LDT + ks * 16 + b_kof) * 2;
                ldm_x4(bfh[ng], st + 2 * TILE_BYTES + bo);
                ldm_x4(bfl[ng], st + 3 * TILE_BYTES + bo);
            }
#pragma unroll
            for (int i = 0; i < 2; i++)
#pragma unroll
                for (int j = 0; j < 8; j++) {
                    const int g = j >> 1, h = (j & 1) * 2;
                    mma16816(acc[i][j], afh[i], bfh[g][h], bfh[g][h + 1]);
                    mma16816(acc[i][j], afh[i], bfl[g][h], bfl[g][h + 1]);
                    mma16816(acc[i][j], afl[i], bfh[g][h], bfh[g][h + 1]);
                }
        }
        __syncthreads();
    }

    const int er = lane >> 2, ec = (lane & 3) * 2;
#pragma unroll
    for (int i = 0; i < 2; i++) {
#pragma unroll
        for (int j = 0; j < 8; j++) {
            int row0 = rowBase + warp_m * 32 + i * 16 + er;
            int col = colBase + warp_n * 64 + j * 8 + ec;
            float2 v0 = make_float2(acc[i][j][0], acc[i][j][1]);
            float2 v1 = make_float2(acc[i][j][2], acc[i][j][3]);
            if (HAS_BIAS) {
                float2 bv = *(const float2*)(bias + col);
                v0.x += bv.x; v0.y += bv.y;
                v1.x += bv.x; v1.y += bv.y;
            }
            *(float2*)(C + (size_t)row0 * N + col) = v0;
            *(float2*)(C + (size_t)(row0 + 8) * N + col) = v1;
        }
    }
}

// ---------------------------------------------------------------------------
// fp32 SGEMM (small K/V projections)
// ---------------------------------------------------------------------------
template <bool HAS_BIAS>
__global__ __launch_bounds__(256) void sgemm128(
    const float* __restrict__ A, const float* __restrict__ B,
    const float* __restrict__ bias, float* __restrict__ C,
    int M, int N, int K)
{
    __shared__ float As[8][128];
    __shared__ float Bs[8][128];
    const int tid = threadIdx.x;
    const int rowBase = blockIdx.y * 128;
    const int colBase = blockIdx.x * 128;
    const int aRow = tid >> 1, aCol = (tid & 1) * 4;
    const int bRow = tid >> 5, bCol = (tid & 31) * 4;
    const int ty = tid >> 4, tx = tid & 15;

    float acc[8][8];
#pragma unroll
    for (int i = 0; i < 8; i++)
#pragma unroll
        for (int j = 0; j < 8; j++) acc[i][j] = 0.f;

    const bool aValid = (rowBase + aRow) < M;
    const float* Aptr = A + (size_t)(rowBase + aRow) * K + aCol;
    const float* Bptr = B + (size_t)bRow * N + colBase + bCol;

    for (int k0 = 0; k0 < K; k0 += 8) {
        float4 av = aValid ? *(const float4*)(Aptr + k0) : make_float4(0, 0, 0, 0);
        float4 bv = *(const float4*)(Bptr + (size_t)k0 * N);
        As[aCol + 0][aRow] = av.x; As[aCol + 1][aRow] = av.y;
        As[aCol + 2][aRow] = av.z; As[aCol + 3][aRow] = av.w;
        *(float4*)&Bs[bRow][bCol] = bv;
        __syncthreads();
#pragma unroll
        for (int kk = 0; kk < 8; kk++) {
            float a[8], b[8];
#pragma unroll
            for (int i = 0; i < 8; i++) a[i] = As[kk][ty * 8 + i];
#pragma unroll
            for (int j = 0; j < 8; j++) b[j] = Bs[kk][tx * 8 + j];
#pragma unroll
            for (int i = 0; i < 8; i++)
#pragma unroll
                for (int j = 0; j < 8; j++) acc[i][j] = fmaf(a[i], b[j], acc[i][j]);
        }
        __syncthreads();
    }
#pragma unroll
    for (int i = 0; i < 8; i++) {
        int r = rowBase + ty * 8 + i;
        if (r >= M) continue;
        float* Cp = C + (size_t)r * N + colBase + tx * 8;
        float outv[8];
#pragma unroll
        for (int j = 0; j < 8; j++) {
            outv[j] = acc[i][j];
            if (HAS_BIAS) outv[j] += bias[colBase + tx * 8 + j];
        }
        *(float4*)(Cp) = *(float4*)(outv);
        *(float4*)(Cp + 4) = *(float4*)(outv + 4);
    }
}

// ---------------------------------------------------------------------------
// Fused attention (float4-vectorized LDS), hi/lo bf16 output.
// ---------------------------------------------------------------------------
__global__ __launch_bounds__(256) void attn_kernel(
    const float* __restrict__ qg, const float* __restrict__ kg,
    const float* __restrict__ vg,
    __nv_bfloat16* __restrict__ ohi, __nv_bfloat16* __restrict__ olo)
{
    extern __shared__ float sm[];
    float* ks = sm;                  // 77 * 68
    float* vs = ks + GC * 68;        // 77 * 68
    float* qs = vs + GC * 68;        // 64 * 64
    float* ws = qs + 64 * 64;        // 64 * 80

    const int n = blockIdx.z, h = blockIdx.y;
    const int qbase = blockIdx.x * 64;
    const int tid = threadIdx.x;
    const int warp = tid >> 5, lane = tid & 31;

    const float* kb = kg + (size_t)n * GC * GD + h * GS;
    const float* vb = vg + (size_t)n * GC * GD + h * GS;
    for (int i = tid; i < GC * GS; i += 256) {
        int c = i >> 6, s = i & 63;
        ks[c * 68 + s] = kb[(size_t)c * GD + s];
        vs[c * 68 + s] = vb[(size_t)c * GD + s];
    }
    const float* qb = qg + ((size_t)n * GQ + qbase) * GD + h * GS;
    for (int i = tid; i < 64 * 64; i += 256) {
        int r = i >> 6, s = i & 63;
        qs[i] = qb[(size_t)r * GD + s] * 0.125f;
    }
    __syncthreads();

    const int r0 = warp * 8;
    const bool c2ok = (lane < GC - 64);

    float sc0[8], sc1[8], sc2[8];
#pragma unroll
    for (int r = 0; r < 8; r++) { sc0[r] = 0.f; sc1[r] = 0.f; sc2[r] = 0.f; }
#pragma unroll
    for (int s = 0; s < 64; s += 4) {
        float4 k0 = *(const float4*)&ks[lane * 68 + s];
        float4 k1 = *(const float4*)&ks[(lane + 32) * 68 + s];
        float4 k2 = c2ok ? *(const float4*)&ks[(lane + 64) * 68 + s]
                         : make_float4(0.f, 0.f, 0.f, 0.f);
#pragma unroll
        for (int r = 0; r < 8; r++) {
            float4 qv = *(const float4*)&qs[(r0 + r) * 64 + s];
            sc0[r] = fmaf(qv.x, k0.x, fmaf(qv.y, k0.y, fmaf(qv.z, k0.z, fmaf(qv.w, k0.w, sc0[r]))));
            sc1[r] = fmaf(qv.x, k1.x, fmaf(qv.y, k1.y, fmaf(qv.z, k1.z, fmaf(qv.w, k1.w, sc1[r]))));
            sc2[r] = fmaf(qv.x, k2.x, fmaf(qv.y, k2.y, fmaf(qv.z, k2.z, fmaf(qv.w, k2.w, sc2[r]))));
        }
    }

#pragma unroll
    for (int r = 0; r < 8; r++) {
        float s2 = c2ok ? sc2[r] : -1e30f;
        float m = fmaxf(fmaxf(sc0[r], sc1[r]), s2);
#pragma unroll
        for (int o = 16; o; o >>= 1) m = fmaxf(m, __shfl_xor_sync(0xffffffffu, m, o));
        float e0 = __expf(sc0[r] - m);
        float e1 = __expf(sc1[r] - m);
        float e2 = c2ok ? __expf(s2 - m) : 0.f;
        float sum = e0 + e1 + e2;
#pragma unroll
        for (int o = 16; o; o >>= 1) sum += __shfl_xor_sync(0xffffffffu, sum, o);
        float inv = __frcp_rn(sum);
        ws[(r0 + r) * 80 + lane] = e0 * inv;
        ws[(r0 + r) * 80 + lane + 32] = e1 * inv;
        if (c2ok) ws[(r0 + r) * 80 + lane + 64] = e2 * inv;
    }
    __syncwarp();

    float a0[8], a1[8];
#pragma unroll
    for (int r = 0; r < 8; r++) { a0[r] = 0.f; a1[r] = 0.f; }
    int c = 0;
    for (; c + 4 <= GC; c += 4) {
        float v0[4], v1[4];
#pragma unroll
        for (int j = 0; j < 4; j++) {
            v0[j] = vs[(c + j) * 68 + lane];
            v1[j] = vs[(c + j) * 68 + lane + 32];
        }
#pragma unroll
        for (int r = 0; r < 8; r++) {
            float4 w = *(const float4*)&ws[(r0 + r) * 80 + c];
            a0[r] = fmaf(w.x, v0[0], fmaf(w.y, v0[1], fmaf(w.z, v0[2], fmaf(w.w, v0[3], a0[r]))));
            a1[r] = fmaf(w.x, v1[0], fmaf(w.y, v1[1], fmaf(w.z, v1[2], fmaf(w.w, v1[3], a1[r]))));
        }
    }
    for (; c < GC; c++) {
        float v0 = vs[c * 68 + lane], v1 = vs[c * 68 + lane + 32];
#pragma unroll
        for (int r = 0; r < 8; r++) {
            float w = ws[(r0 + r) * 80 + c];
            a0[r] = fmaf(w, v0, a0[r]);
            a1[r] = fmaf(w, v1, a1[r]);
        }
    }

    size_t base = ((size_t)n * GQ + qbase) * GD + h * GS;
#pragma unroll
    for (int r = 0; r < 8; r++) {
        size_t o = base + (size_t)(r0 + r) * GD;
        __nv_bfloat16 h0, l0, h1, l1;
        split_bf16(a0[r], h0, l0);
        split_bf16(a1[r], h1, l1);
        ohi[o + lane] = h0;       olo[o + lane] = l0;
        ohi[o + lane + 32] = h1;  olo[o + lane + 32] = l1;
    }
}

// ---------------------------------------------------------------------------
__global__ void conv_split(const float* __restrict__ in,
                           __nv_bfloat16* __restrict__ hi,
                           __nv_bfloat16* __restrict__ lo, int n)
{
    int i = (blockIdx.x * blockDim.x + threadIdx.x) * 4;
    int stride = gridDim.x * blockDim.x * 4;
    for (; i < n; i += stride) {
        float4 v = *(const float4*)(in + i);
        __nv_bfloat16 h[4], l[4];
        split_bf16(v.x, h[0], l[0]);
        split_bf16(v.y, h[1], l[1]);
        split_bf16(v.z, h[2], l[2]);
        split_bf16(v.w, h[3], l[3]);
        *(uint2*)(hi + i) = *(uint2*)h;
        *(uint2*)(lo + i) = *(uint2*)l;
    }
}

// W[K][N] fp32 -> Wt[N][K] hi/lo bf16
__global__ void transpose_split(const float* __restrict__ W,
                                __nv_bfloat16* __restrict__ Whi,
                                __nv_bfloat16* __restrict__ Wlo, int K, int N)
{
    __shared__ float t[32][33];
    int k0 = blockIdx.y * 32, n0 = blockIdx.x * 32;
    int x = threadIdx.x, y = threadIdx.y;  // 32 x 8
#pragma unroll
    for (int i = 0; i < 32; i += 8) t[y + i][x] = W[(size_t)(k0 + y + i) * N + n0 + x];
    __syncthreads();
#pragma unroll
    for (int i = 0; i < 32; i += 8) {
        __nv_bfloat16 h, l;
        split_bf16(t[x][y + i], h, l);
        Whi[(size_t)(n0 + y + i) * K + k0 + x] = h;
        Wlo[(size_t)(n0 + y + i) * K + k0 + x] = l;
    }
}

// ---------------------------------------------------------------------------
extern "C" void kernel_launch(void* const* d_in, const int* in_sizes, int n_in,
                              void* d_out, int out_size)
{
    const float* query   = (const float*)d_in[0];
    const float* context = (const float*)d_in[1];
    const float* Wq      = (const float*)d_in[2];
    const float* Wk      = (const float*)d_in[3];
    const float* Wv      = (const float*)d_in[4];
    const float* Wo      = (const float*)d_in[5];
    const float* bo      = (const float*)d_in[6];
    float* out = (float*)d_out;

    void *pq, *pk, *pv;
    void *pqh, *pql, *pah, *pal, *pwqh, *pwql, *pwoh, *pwol;
    cudaGetSymbolAddress(&pq, g_q);
    cudaGetSymbolAddress(&pk, g_k);
    cudaGetSymbolAddress(&pv, g_v);
    cudaGetSymbolAddress(&pqh, g_qhi);
    cudaGetSymbolAddress(&pql, g_qlo);
    cudaGetSymbolAddress(&pah, g_ahi);
    cudaGetSymbolAddress(&pal, g_alo);
    cudaGetSymbolAddress(&pwqh, g_wqT_hi);
    cudaGetSymbolAddress(&pwql, g_wqT_lo);
    cudaGetSymbolAddress(&pwoh, g_woT_hi);
    cudaGetSymbolAddress(&pwol, g_woT_lo);

    cudaFuncSetAttribute(gemm_mma3<false>, cudaFuncAttributeMaxDynamicSharedMemorySize, GEMM_SMEM);
    cudaFuncSetAttribute(gemm_mma3<true>,  cudaFuncAttributeMaxDynamicSharedMemorySize, GEMM_SMEM);

    // prep: query -> hi/lo, W transposes -> hi/lo
    conv_split<<<1024, 256>>>(query, (__nv_bfloat16*)pqh, (__nv_bfloat16*)pql, GM * GD);
    {
        dim3 b(32, 8);
        transpose_split<<<dim3(GD / 32, GD / 32), b>>>(Wq, (__nv_bfloat16*)pwqh,
                                                       (__nv_bfloat16*)pwql, GD, GD);
        transpose_split<<<dim3(GD / 32, GD / 32), b>>>(Wo, (__nv_bfloat16*)pwoh,
                                                       (__nv_bfloat16*)pwol, GD, GD);
    }
    // K/V projections (fp32)
    {
        dim3 grid(GD / 128, (GN * GC + 127) / 128);
        sgemm128<false><<<grid, 256>>>(context, Wk, nullptr, (float*)pk, GN * GC, GD, GDC);
        sgemm128<false><<<grid, 256>>>(context, Wv, nullptr, (float*)pv, GN * GC, GD, GDC);
    }
    // Q projection (bf16x3 tensor cores)
    {
        dim3 grid(GD / 128, GM / 128);
        gemm_mma3<false><<<grid, 256, GEMM_SMEM>>>(
            (const __nv_bfloat16*)pqh, (const __nv_bfloat16*)pql,
            (const __nv_bfloat16*)pwqh, (const __nv_bfloat16*)pwql,
            nullptr, (float*)pq, GM, GD, GD);
    }
    // attention (hi/lo out)
    {
        int smem = (GC * 68 * 2 + 64 * 64 + 64 * 80) * (int)sizeof(float);
        cudaFuncSetAttribute(attn_kernel, cudaFuncAttributeMaxDynamicSharedMemorySize, smem);
        dim3 grid(GQ / 64, GH, GN);
        attn_kernel<<<grid, 256, smem>>>((const float*)pq, (const float*)pk,
                                         (const float*)pv,
                                         (__nv_bfloat16*)pah, (__nv_bfloat16*)pal);
    }
    // O projection + bias (bf16x3 tensor cores)
    {
        dim3 grid(GD / 128, GM / 128);
        gemm_mma3<true><<<grid, 256, GEMM_SMEM>>>(
            (const __nv_bfloat16*)pah, (const __nv_bfloat16*)pal,
            (const __nv_bfloat16*)pwoh, (const __nv_bfloat16*)pwol,
            bo, out, GM, GD, GD);
    }
}

// round 5
// speedup vs baseline: 2.0190x; 1.1887x over previous
#include <cuda_runtime.h>
#include <cuda_bf16.h>
#include <cstdint>

#define GN 16
#define GQ 4096
#define GC 77
#define GD 512
#define GDC 768
#define GH 8
#define GS 64
#define GM (GN * GQ)  // 65536

// ---------------- scratch (device globals, allocation-free) ----------------
__device__ float g_q[(size_t)GM * GD];               // fp32 q after projection
__device__ float g_att[(size_t)GM * GD];             // fp32 attn output
__device__ float g_k[(size_t)GN * GC * GD];
__device__ float g_v[(size_t)GN * GC * GD];
__device__ __nv_bfloat16 g_wqT_hi[GD * GD], g_wqT_lo[GD * GD];  // Wq^T [N][K]
__device__ __nv_bfloat16 g_woT_hi[GD * GD], g_woT_lo[GD * GD];  // Wo^T [N][K]

__device__ __forceinline__ uint32_t smem_u32(const void* p) {
    uint32_t a;
    asm("{ .reg .u64 t; cvta.to.shared.u64 t, %1; cvt.u32.u64 %0, t; }"
        : "=r"(a) : "l"(p));
    return a;
}
__device__ __forceinline__ void cp_async16(uint32_t dst, const void* src) {
    asm volatile("cp.async.cg.shared.global [%0], [%1], 16;"
                 :: "r"(dst), "l"(src) : "memory");
}
#define CP_COMMIT() asm volatile("cp.async.commit_group;" ::: "memory")

__device__ __forceinline__ void ldm_x4(uint32_t (&f)[4], uint32_t addr) {
    asm volatile("ldmatrix.sync.aligned.m8n8.x4.shared.b16 {%0,%1,%2,%3}, [%4];"
                 : "=r"(f[0]), "=r"(f[1]), "=r"(f[2]), "=r"(f[3]) : "r"(addr));
}
__device__ __forceinline__ void mma16816(float (&d)[4], const uint32_t (&a)[4],
                                         uint32_t b0, uint32_t b1) {
    asm volatile(
        "mma.sync.aligned.m16n8k16.row.col.f32.bf16.bf16.f32 "
        "{%0,%1,%2,%3}, {%4,%5,%6,%7}, {%8,%9}, {%0,%1,%2,%3};"
        : "+f"(d[0]), "+f"(d[1]), "+f"(d[2]), "+f"(d[3])
        : "r"(a[0]), "r"(a[1]), "r"(a[2]), "r"(a[3]), "r"(b0), "r"(b1));
}

__device__ __forceinline__ void split_bf16(float x, __nv_bfloat16& hi, __nv_bfloat16& lo) {
    hi = __float2bfloat16_rn(x);
    lo = __float2bfloat16_rn(x - __bfloat162float(hi));
}

// ---------------------------------------------------------------------------
// bf16x3 mma.sync GEMM, fp32 A input (split to hi/lo in-kernel via LDG+STS).
// C = A*Bt^T (+bias). Bt supplied pre-split (hi/lo bf16, [N][K]).
// 128x128 block, BK=32, 8 warps (4x2), warp tile 32x64, double-buffered.
// Smem tile rows padded to LDT=40 bf16 (80B) => conflict-free ldmatrix.
// Requires M%128==0, N%128==0, K%32==0.
// ---------------------------------------------------------------------------
#define LDT 40
#define TILE_B (128 * LDT)
#define TILE_BYTES (TILE_B * 2)       // 10240 B per bf16 tile
#define STAGE_BYTES (4 * TILE_BYTES)  // Ahi, Alo, Bhi, Blo
#define GEMM_SMEM (2 * STAGE_BYTES)   // 81920 B

template <bool HAS_BIAS>
__global__ __launch_bounds__(256) void gemm_mma3f(
    const float* __restrict__ A,
    const __nv_bfloat16* __restrict__ Bhi, const __nv_bfloat16* __restrict__ Blo,
    const float* __restrict__ bias, float* __restrict__ C,
    int M, int N, int K)
{
    extern __shared__ __align__(16) char gsm[];
    const uint32_t sa = smem_u32(gsm);

    const int tid = threadIdx.x;
    const int wid = tid >> 5, lane = tid & 31;
    const int warp_m = wid & 3;
    const int warp_n = wid >> 2;
    const int rowBase = blockIdx.y * 128;
    const int colBase = blockIdx.x * 128;

    const float* Ab = A + (size_t)rowBase * K;
    const size_t bOff = (size_t)colBase * K;

    // A loads: tile = 128 rows x 32 k fp32 = 1024 float4 chunks, 4 per thread.
    // chunk c: row = c>>3, kc = (c&7)*4
    // B loads: tile = 128 rows x 32 k bf16 = 512 16B chunks, 2 per thread.
    const int ldr0 = tid >> 2, ldc0 = (tid & 3);
    const int ldr1 = (tid + 256) >> 2, ldc1 = (tid & 3);

    const int q = lane >> 3, r = lane & 7;
    const int a_row = warp_m * 32 + ((q & 1) * 8) + r;
    const int a_kof = (q >> 1) * 8;
    const int b_row = warp_n * 64 + ((q >> 1) * 8) + r;
    const int b_kof = (q & 1) * 8;

    float acc[2][8][4];
#pragma unroll
    for (int i = 0; i < 2; i++)
#pragma unroll
        for (int j = 0; j < 8; j++)
#pragma unroll
            for (int t = 0; t < 4; t++) acc[i][j][t] = 0.f;

    const int NC = K >> 5;

    auto load_A = [&](int c) {   // LDG fp32, split, STS hi/lo
        const int k0 = c << 5;
        const uint32_t st = sa + (c & 1) * STAGE_BYTES;
#pragma unroll
        for (int i = 0; i < 4; i++) {
            int ch = tid + i * 256;
            int row = ch >> 3, kc = (ch & 7) * 4;
            float4 v = *(const float4*)(Ab + (size_t)row * K + k0 + kc);
            __nv_bfloat16 h[4], l[4];
            split_bf16(v.x, h[0], l[0]);
            split_bf16(v.y, h[1], l[1]);
            split_bf16(v.z, h[2], l[2]);
            split_bf16(v.w, h[3], l[3]);
            uint32_t off = (row * LDT + kc) * 2;
            *(uint2*)(gsm + (st - sa) + off) = *(uint2*)h;                 // Ahi
            *(uint2*)(gsm + (st - sa) + TILE_BYTES + off) = *(uint2*)l;    // Alo
        }
    };
    auto load_B = [&](int c) {   // cp.async bf16 hi/lo
        const int k0 = c << 5;
        const uint32_t st = sa + (c & 1) * STAGE_BYTES;
        const uint32_t o0 = (ldr0 * LDT + ldc0 * 8) * 2;
        const uint32_t o1 = (ldr1 * LDT + ldc1 * 8) * 2;
        const size_t g0 = (size_t)ldr0 * K + k0 + ldc0 * 8;
        const size_t g1 = (size_t)ldr1 * K + k0 + ldc1 * 8;
        cp_async16(st + 2 * TILE_BYTES + o0, Bhi + bOff + g0);
        cp_async16(st + 2 * TILE_BYTES + o1, Bhi + bOff + g1);
        cp_async16(st + 3 * TILE_BYTES + o0, Blo + bOff + g0);
        cp_async16(st + 3 * TILE_BYTES + o1, Blo + bOff + g1);
        CP_COMMIT();
    };

    load_B(0);
    load_A(0);

    for (int c = 0; c < NC; c++) {
        if (c + 1 < NC) {
            load_B(c + 1);
            load_A(c + 1);
            asm volatile("cp.async.wait_group 1;" ::: "memory");
        } else {
            asm volatile("cp.async.wait_group 0;" ::: "memory");
        }
        __syncthreads();   // stage c tiles visible

        const uint32_t st = sa + (c & 1) * STAGE_BYTES;
#pragma unroll
        for (int ks = 0; ks < 2; ks++) {
            uint32_t afh[2][4], afl[2][4];
#pragma unroll
            for (int i = 0; i < 2; i++) {
                uint32_t ao = ((a_row + i * 16) * LDT + ks * 16 + a_kof) * 2;
                ldm_x4(afh[i], st + ao);
                ldm_x4(afl[i], st + TILE_BYTES + ao);
            }
            uint32_t bfh[4][4], bfl[4][4];
#pragma unroll
            for (int ng = 0; ng < 4; ng++) {
                uint32_t bo = ((b_row + ng * 16) * LDT + ks * 16 + b_kof) * 2;
                ldm_x4(bfh[ng], st + 2 * TILE_BYTES + bo);
                ldm_x4(bfl[ng], st + 3 * TILE_BYTES + bo);
            }
#pragma unroll
            for (int i = 0; i < 2; i++)
#pragma unroll
                for (int j = 0; j < 8; j++) {
                    const int g = j >> 1, h = (j & 1) * 2;
                    mma16816(acc[i][j], afh[i], bfh[g][h], bfh[g][h + 1]);
                    mma16816(acc[i][j], afh[i], bfl[g][h], bfl[g][h + 1]);
                    mma16816(acc[i][j], afl[i], bfh[g][h], bfh[g][h + 1]);
                }
        }
        __syncthreads();   // done reading stage c (its buffers rewritten at c+2)
    }

    const int er = lane >> 2, ec = (lane & 3) * 2;
#pragma unroll
    for (int i = 0; i < 2; i++) {
#pragma unroll
        for (int j = 0; j < 8; j++) {
            int row0 = rowBase + warp_m * 32 + i * 16 + er;
            int col = colBase + warp_n * 64 + j * 8 + ec;
            float2 v0 = make_float2(acc[i][j][0], acc[i][j][1]);
            float2 v1 = make_float2(acc[i][j][2], acc[i][j][3]);
            if (HAS_BIAS) {
                float2 bv = *(const float2*)(bias + col);
                v0.x += bv.x; v0.y += bv.y;
                v1.x += bv.x; v1.y += bv.y;
            }
            *(float2*)(C + (size_t)row0 * N + col) = v0;
            *(float2*)(C + (size_t)(row0 + 8) * N + col) = v1;
        }
    }
}

// ---------------------------------------------------------------------------
// fp32 SGEMM, 64x64 tiles (K/V projections: M=1232 -> 160 blocks)
// 256 threads, 4x4 microtile, BK=16. N%64==0, K%16==0; M guarded.
// ---------------------------------------------------------------------------
__global__ __launch_bounds__(256) void sgemm64(
    const float* __restrict__ A, const float* __restrict__ B,
    float* __restrict__ C, int M, int N, int K)
{
    __shared__ float As[16][68];  // [k][row]
    __shared__ float Bs[16][68];  // [k][col]
    const int tid = threadIdx.x;
    const int rowBase = blockIdx.y * 64;
    const int colBase = blockIdx.x * 64;
    const int aRow = tid >> 2, aCol = (tid & 3) * 4;   // A: 64 rows x 16 k
    const int bRow = tid >> 4, bCol = (tid & 15) * 4;  // B: 16 k x 64 cols
    const int ty = tid >> 4, tx = tid & 15;

    float acc[4][4];
#pragma unroll
    for (int i = 0; i < 4; i++)
#pragma unroll
        for (int j = 0; j < 4; j++) acc[i][j] = 0.f;

    const bool aValid = (rowBase + aRow) < M;
    const float* Aptr = A + (size_t)(rowBase + aRow) * K + aCol;
    const float* Bptr = B + (size_t)bRow * N + colBase + bCol;

    for (int k0 = 0; k0 < K; k0 += 16) {
        float4 av = aValid ? *(const float4*)(Aptr + k0) : make_float4(0, 0, 0, 0);
        float4 bv = *(const float4*)(Bptr + (size_t)k0 * N);
        As[aCol + 0][aRow] = av.x; As[aCol + 1][aRow] = av.y;
        As[aCol + 2][aRow] = av.z; As[aCol + 3][aRow] = av.w;
        *(float4*)&Bs[bRow][bCol] = bv;
        __syncthreads();
#pragma unroll
        for (int kk = 0; kk < 16; kk++) {
            float a[4], b[4];
#pragma unroll
            for (int i = 0; i < 4; i++) a[i] = As[kk][ty * 4 + i];
#pragma unroll
            for (int j = 0; j < 4; j++) b[j] = Bs[kk][tx * 4 + j];
#pragma unroll
            for (int i = 0; i < 4; i++)
#pragma unroll
                for (int j = 0; j < 4; j++) acc[i][j] = fmaf(a[i], b[j], acc[i][j]);
        }
        __syncthreads();
    }
#pragma unroll
    for (int i = 0; i < 4; i++) {
        int rr = rowBase + ty * 4 + i;
        if (rr >= M) continue;
        *(float4*)(C + (size_t)rr * N + colBase + tx * 4) = *(float4*)acc[i];
    }
}

// ---------------------------------------------------------------------------
// Fused attention (float4-vectorized LDS), fp32 output.
// ---------------------------------------------------------------------------
__global__ __launch_bounds__(256) void attn_kernel(
    const float* __restrict__ qg, const float* __restrict__ kg,
    const float* __restrict__ vg, float* __restrict__ og)
{
    extern __shared__ float sm[];
    float* ks = sm;                  // 77 * 68
    float* vs = ks + GC * 68;        // 77 * 68
    float* qs = vs + GC * 68;        // 64 * 64
    float* ws = qs + 64 * 64;        // 64 * 80

    const int n = blockIdx.z, h = blockIdx.y;
    const int qbase = blockIdx.x * 64;
    const int tid = threadIdx.x;
    const int warp = tid >> 5, lane = tid & 31;

    const float* kb = kg + (size_t)n * GC * GD + h * GS;
    const float* vb = vg + (size_t)n * GC * GD + h * GS;
    for (int i = tid; i < GC * GS; i += 256) {
        int c = i >> 6, s = i & 63;
        ks[c * 68 + s] = kb[(size_t)c * GD + s];
        vs[c * 68 + s] = vb[(size_t)c * GD + s];
    }
    const float* qb = qg + ((size_t)n * GQ + qbase) * GD + h * GS;
    for (int i = tid; i < 64 * 64; i += 256) {
        int r = i >> 6, s = i & 63;
        qs[i] = qb[(size_t)r * GD + s] * 0.125f;
    }
    __syncthreads();

    const int r0 = warp * 8;
    const bool c2ok = (lane < GC - 64);

    float sc0[8], sc1[8], sc2[8];
#pragma unroll
    for (int r = 0; r < 8; r++) { sc0[r] = 0.f; sc1[r] = 0.f; sc2[r] = 0.f; }
#pragma unroll
    for (int s = 0; s < 64; s += 4) {
        float4 k0 = *(const float4*)&ks[lane * 68 + s];
        float4 k1 = *(const float4*)&ks[(lane + 32) * 68 + s];
        float4 k2 = c2ok ? *(const float4*)&ks[(lane + 64) * 68 + s]
                         : make_float4(0.f, 0.f, 0.f, 0.f);
#pragma unroll
        for (int r = 0; r < 8; r++) {
            float4 qv = *(const float4*)&qs[(r0 + r) * 64 + s];
            sc0[r] = fmaf(qv.x, k0.x, fmaf(qv.y, k0.y, fmaf(qv.z, k0.z, fmaf(qv.w, k0.w, sc0[r]))));
            sc1[r] = fmaf(qv.x, k1.x, fmaf(qv.y, k1.y, fmaf(qv.z, k1.z, fmaf(qv.w, k1.w, sc1[r]))));
            sc2[r] = fmaf(qv.x, k2.x, fmaf(qv.y, k2.y, fmaf(qv.z, k2.z, fmaf(qv.w, k2.w, sc2[r]))));
        }
    }

#pragma unroll
    for (int r = 0; r < 8; r++) {
        float s2 = c2ok ? sc2[r] : -1e30f;
        float m = fmaxf(fmaxf(sc0[r], sc1[r]), s2);
#pragma unroll
        for (int o = 16; o; o >>= 1) m = fmaxf(m, __shfl_xor_sync(0xffffffffu, m, o));
        float e0 = __expf(sc0[r] - m);
        float e1 = __expf(sc1[r] - m);
        float e2 = c2ok ? __expf(s2 - m) : 0.f;
        float sum = e0 + e1 + e2;
#pragma unroll
        for (int o = 16; o; o >>= 1) sum += __shfl_xor_sync(0xffffffffu, sum, o);
        float inv = __frcp_rn(sum);
        ws[(r0 + r) * 80 + lane] = e0 * inv;
        ws[(r0 + r) * 80 + lane + 32] = e1 * inv;
        if (c2ok) ws[(r0 + r) * 80 + lane + 64] = e2 * inv;
    }
    __syncwarp();

    float a0[8], a1[8];
#pragma unroll
    for (int r = 0; r < 8; r++) { a0[r] = 0.f; a1[r] = 0.f; }
    int c = 0;
    for (; c + 4 <= GC; c += 4) {
        float v0[4], v1[4];
#pragma unroll
        for (int j = 0; j < 4; j++) {
            v0[j] = vs[(c + j) * 68 + lane];
            v1[j] = vs[(c + j) * 68 + lane + 32];
        }
#pragma unroll
        for (int r = 0; r < 8; r++) {
            float4 w = *(const float4*)&ws[(r0 + r) * 80 + c];
            a0[r] = fmaf(w.x, v0[0], fmaf(w.y, v0[1], fmaf(w.z, v0[2], fmaf(w.w, v0[3], a0[r]))));
            a1[r] = fmaf(w.x, v1[0], fmaf(w.y, v1[1], fmaf(w.z, v1[2], fmaf(w.w, v1[3], a1[r]))));
        }
    }
    for (; c < GC; c++) {
        float v0 = vs[c * 68 + lane], v1 = vs[c * 68 + lane + 32];
#pragma unroll
        for (int r = 0; r < 8; r++) {
            float w = ws[(r0 + r) * 80 + c];
            a0[r] = fmaf(w, v0, a0[r]);
            a1[r] = fmaf(w, v1, a1[r]);
        }
    }

    float* ob = og + ((size_t)n * GQ + qbase) * GD + h * GS;
#pragma unroll
    for (int r = 0; r < 8; r++) {
        ob[(size_t)(r0 + r) * GD + lane] = a0[r];
        ob[(size_t)(r0 + r) * GD + lane + 32] = a1[r];
    }
}

// ---------------------------------------------------------------------------
// W[K][N] fp32 -> Wt[N][K] hi/lo bf16
__global__ void transpose_split(const float* __restrict__ W,
                                __nv_bfloat16* __restrict__ Whi,
                                __nv_bfloat16* __restrict__ Wlo, int K, int N)
{
    __shared__ float t[32][33];
    int k0 = blockIdx.y * 32, n0 = blockIdx.x * 32;
    int x = threadIdx.x, y = threadIdx.y;  // 32 x 8
#pragma unroll
    for (int i = 0; i < 32; i += 8) t[y + i][x] = W[(size_t)(k0 + y + i) * N + n0 + x];
    __syncthreads();
#pragma unroll
    for (int i = 0; i < 32; i += 8) {
        __nv_bfloat16 h, l;
        split_bf16(t[x][y + i], h, l);
        Whi[(size_t)(n0 + y + i) * K + k0 + x] = h;
        Wlo[(size_t)(n0 + y + i) * K + k0 + x] = l;
    }
}

// ---------------------------------------------------------------------------
extern "C" void kernel_launch(void* const* d_in, const int* in_sizes, int n_in,
                              void* d_out, int out_size)
{
    const float* query   = (const float*)d_in[0];
    const float* context = (const float*)d_in[1];
    const float* Wq      = (const float*)d_in[2];
    const float* Wk      = (const float*)d_in[3];
    const float* Wv      = (const float*)d_in[4];
    const float* Wo      = (const float*)d_in[5];
    const float* bo      = (const float*)d_in[6];
    float* out = (float*)d_out;

    void *pq, *pa, *pk, *pv, *pwqh, *pwql, *pwoh, *pwol;
    cudaGetSymbolAddress(&pq, g_q);
    cudaGetSymbolAddress(&pa, g_att);
    cudaGetSymbolAddress(&pk, g_k);
    cudaGetSymbolAddress(&pv, g_v);
    cudaGetSymbolAddress(&pwqh, g_wqT_hi);
    cudaGetSymbolAddress(&pwql, g_wqT_lo);
    cudaGetSymbolAddress(&pwoh, g_woT_hi);
    cudaGetSymbolAddress(&pwol, g_woT_lo);

    cudaFuncSetAttribute(gemm_mma3f<false>, cudaFuncAttributeMaxDynamicSharedMemorySize, GEMM_SMEM);
    cudaFuncSetAttribute(gemm_mma3f<true>,  cudaFuncAttributeMaxDynamicSharedMemorySize, GEMM_SMEM);

    // prep: W transposes -> hi/lo (tiny)
    {
        dim3 b(32, 8);
        transpose_split<<<dim3(GD / 32, GD / 32), b>>>(Wq, (__nv_bfloat16*)pwqh,
                                                       (__nv_bfloat16*)pwql, GD, GD);
        transpose_split<<<dim3(GD / 32, GD / 32), b>>>(Wo, (__nv_bfloat16*)pwoh,
                                                       (__nv_bfloat16*)pwol, GD, GD);
    }
    // K/V projections (fp32, 64x64 tiles -> 160 blocks)
    {
        dim3 grid(GD / 64, (GN * GC + 63) / 64);
        sgemm64<<<grid, 256>>>(context, Wk, (float*)pk, GN * GC, GD, GDC);
        sgemm64<<<grid, 256>>>(context, Wv, (float*)pv, GN * GC, GD, GDC);
    }
    // Q projection (bf16x3 tensor cores, fp32 A direct)
    {
        dim3 grid(GD / 128, GM / 128);
        gemm_mma3f<false><<<grid, 256, GEMM_SMEM>>>(
            query, (const __nv_bfloat16*)pwqh, (const __nv_bfloat16*)pwql,
            nullptr, (float*)pq, GM, GD, GD);
    }
    // attention (fp32 out)
    {
        int smem = (GC * 68 * 2 + 64 * 64 + 64 * 80) * (int)sizeof(float);
        cudaFuncSetAttribute(attn_kernel, cudaFuncAttributeMaxDynamicSharedMemorySize, smem);
        dim3 grid(GQ / 64, GH, GN);
        attn_kernel<<<grid, 256, smem>>>((const float*)pq, (const float*)pk,
                                         (const float*)pv, (float*)pa);
    }
    // O projection + bias (bf16x3 tensor cores, fp32 A direct)
    {
        dim3 grid(GD / 128, GM / 128);
        gemm_mma3f<true><<<grid, 256, GEMM_SMEM>>>(
            (const float*)pa, (const __nv_bfloat16*)pwoh, (const __nv_bfloat16*)pwol,
            bo, out, GM, GD, GD);
    }
}

// round 6
// speedup vs baseline: 2.2142x; 1.0967x over previous
#include <cuda_runtime.h>
#include <cuda_bf16.h>
#include <cstdint>

#define GN 16
#define GQ 4096
#define GC 77
#define GD 512
#define GDC 768
#define GH 8
#define GS 64
#define GM (GN * GQ)  // 65536

// ---------------- scratch (device globals, allocation-free) ----------------
__device__ float g_q[(size_t)GM * GD];               // fp32 q after projection
__device__ float g_att[(size_t)GM * GD];             // fp32 attn output
__device__ float g_k[(size_t)GN * GC * GD];
__device__ float g_v[(size_t)GN * GC * GD];
__device__ __nv_bfloat16 g_wqT_hi[GD * GD], g_wqT_lo[GD * GD];  // Wq^T [N][K]
__device__ __nv_bfloat16 g_woT_hi[GD * GD], g_woT_lo[GD * GD];  // Wo^T [N][K]

__device__ __forceinline__ uint32_t smem_u32(const void* p) {
    uint32_t a;
    asm("{ .reg .u64 t; cvta.to.shared.u64 t, %1; cvt.u32.u64 %0, t; }"
        : "=r"(a) : "l"(p));
    return a;
}
__device__ __forceinline__ void cp_async16(uint32_t dst, const void* src) {
    asm volatile("cp.async.cg.shared.global [%0], [%1], 16;"
                 :: "r"(dst), "l"(src) : "memory");
}
#define CP_COMMIT() asm volatile("cp.async.commit_group;" ::: "memory")

__device__ __forceinline__ void ldm_x4(uint32_t (&f)[4], uint32_t addr) {
    asm volatile("ldmatrix.sync.aligned.m8n8.x4.shared.b16 {%0,%1,%2,%3}, [%4];"
                 : "=r"(f[0]), "=r"(f[1]), "=r"(f[2]), "=r"(f[3]) : "r"(addr));
}
__device__ __forceinline__ void mma16816(float (&d)[4], const uint32_t (&a)[4],
                                         uint32_t b0, uint32_t b1) {
    asm volatile(
        "mma.sync.aligned.m16n8k16.row.col.f32.bf16.bf16.f32 "
        "{%0,%1,%2,%3}, {%4,%5,%6,%7}, {%8,%9}, {%0,%1,%2,%3};"
        : "+f"(d[0]), "+f"(d[1]), "+f"(d[2]), "+f"(d[3])
        : "r"(a[0]), "r"(a[1]), "r"(a[2]), "r"(a[3]), "r"(b0), "r"(b1));
}

__device__ __forceinline__ void split_bf16(float x, __nv_bfloat16& hi, __nv_bfloat16& lo) {
    hi = __float2bfloat16_rn(x);
    lo = __float2bfloat16_rn(x - __bfloat162float(hi));
}

// ---------------------------------------------------------------------------
// bf16x3 mma.sync GEMM, fp32 A input. Pipelined: A LDG->regs overlaps compute.
// C = A*Bt^T (+bias). Bt pre-split (hi/lo bf16, [N][K]).
// 128x128 block, BK=32, 8 warps (4x2), warp tile 32x64, double-buffered.
// ---------------------------------------------------------------------------
#define LDT 40
#define TILE_B (128 * LDT)
#define TILE_BYTES (TILE_B * 2)       // 10240 B per bf16 tile
#define STAGE_BYTES (4 * TILE_BYTES)  // Ahi, Alo, Bhi, Blo
#define GEMM_SMEM (2 * STAGE_BYTES)   // 81920 B

template <bool HAS_BIAS>
__global__ __launch_bounds__(256) void gemm_mma3f(
    const float* __restrict__ A,
    const __nv_bfloat16* __restrict__ Bhi, const __nv_bfloat16* __restrict__ Blo,
    const float* __restrict__ bias, float* __restrict__ C,
    int M, int N, int K)
{
    extern __shared__ __align__(16) char gsm[];
    const uint32_t sa = smem_u32(gsm);

    const int tid = threadIdx.x;
    const int wid = tid >> 5, lane = tid & 31;
    const int warp_m = wid & 3;
    const int warp_n = wid >> 2;
    const int rowBase = blockIdx.y * 128;
    const int colBase = blockIdx.x * 128;

    const float* Ab = A + (size_t)rowBase * K;
    const size_t bOff = (size_t)colBase * K;

    const int ldr0 = tid >> 2, ldc0 = (tid & 3);
    const int ldr1 = (tid + 256) >> 2, ldc1 = (tid & 3);

    const int q = lane >> 3, r = lane & 7;
    const int a_row = warp_m * 32 + ((q & 1) * 8) + r;
    const int a_kof = (q >> 1) * 8;
    const int b_row = warp_n * 64 + ((q >> 1) * 8) + r;
    const int b_kof = (q & 1) * 8;

    float acc[2][8][4];
#pragma unroll
    for (int i = 0; i < 2; i++)
#pragma unroll
        for (int j = 0; j < 8; j++)
#pragma unroll
            for (int t = 0; t < 4; t++) acc[i][j][t] = 0.f;

    const int NC = K >> 5;

    // A: tile = 128 rows x 32 k fp32 = 1024 float4 chunks, 4 per thread.
    float4 areg[4];
    auto ldg_A = [&](int c) {
        const int k0 = c << 5;
#pragma unroll
        for (int i = 0; i < 4; i++) {
            int ch = tid + i * 256;
            int row = ch >> 3, kc = (ch & 7) * 4;
            areg[i] = *(const float4*)(Ab + (size_t)row * K + k0 + kc);
        }
    };
    auto sts_A = [&](int c) {
        const uint32_t st = (c & 1) * STAGE_BYTES;
#pragma unroll
        for (int i = 0; i < 4; i++) {
            int ch = tid + i * 256;
            int row = ch >> 3, kc = (ch & 7) * 4;
            __nv_bfloat16 h[4], l[4];
            split_bf16(areg[i].x, h[0], l[0]);
            split_bf16(areg[i].y, h[1], l[1]);
            split_bf16(areg[i].z, h[2], l[2]);
            split_bf16(areg[i].w, h[3], l[3]);
            uint32_t off = (row * LDT + kc) * 2;
            *(uint2*)(gsm + st + off) = *(uint2*)h;
            *(uint2*)(gsm + st + TILE_BYTES + off) = *(uint2*)l;
        }
    };
    auto load_B = [&](int c) {
        const int k0 = c << 5;
        const uint32_t st = sa + (c & 1) * STAGE_BYTES;
        const uint32_t o0 = (ldr0 * LDT + ldc0 * 8) * 2;
        const uint32_t o1 = (ldr1 * LDT + ldc1 * 8) * 2;
        const size_t g0 = (size_t)ldr0 * K + k0 + ldc0 * 8;
        const size_t g1 = (size_t)ldr1 * K + k0 + ldc1 * 8;
        cp_async16(st + 2 * TILE_BYTES + o0, Bhi + bOff + g0);
        cp_async16(st + 2 * TILE_BYTES + o1, Bhi + bOff + g1);
        cp_async16(st + 3 * TILE_BYTES + o0, Blo + bOff + g0);
        cp_async16(st + 3 * TILE_BYTES + o1, Blo + bOff + g1);
        CP_COMMIT();
    };

    // prologue: stage 0 fully resident
    ldg_A(0);
    load_B(0);
    sts_A(0);

    for (int c = 0; c < NC; c++) {
        if (c + 1 < NC) {
            ldg_A(c + 1);        // LDG in flight during compute(c)
            load_B(c + 1);
            asm volatile("cp.async.wait_group 1;" ::: "memory");
        } else {
            asm volatile("cp.async.wait_group 0;" ::: "memory");
        }
        __syncthreads();  // stage c visible to all; all warps past compute(c-1)

        const uint32_t st = sa + (c & 1) * STAGE_BYTES;
#pragma unroll
        for (int ks = 0; ks < 2; ks++) {
            uint32_t afh[2][4], afl[2][4];
#pragma unroll
            for (int i = 0; i < 2; i++) {
                uint32_t ao = ((a_row + i * 16) * LDT + ks * 16 + a_kof) * 2;
                ldm_x4(afh[i], st + ao);
                ldm_x4(afl[i], st + TILE_BYTES + ao);
            }
            uint32_t bfh[4][4], bfl[4][4];
#pragma unroll
            for (int ng = 0; ng < 4; ng++) {
                uint32_t bo = ((b_row + ng * 16) * LDT + ks * 16 + b_kof) * 2;
                ldm_x4(bfh[ng], st + 2 * TILE_BYTES + bo);
                ldm_x4(bfl[ng], st + 3 * TILE_BYTES + bo);
            }
#pragma unroll
            for (int i = 0; i < 2; i++)
#pragma unroll
                for (int j = 0; j < 8; j++) {
                    const int g = j >> 1, h = (j & 1) * 2;
                    mma16816(acc[i][j], afh[i], bfh[g][h], bfh[g][h + 1]);
                    mma16816(acc[i][j], afh[i], bfl[g][h], bfl[g][h + 1]);
                    mma16816(acc[i][j], afl[i], bfh[g][h], bfh[g][h + 1]);
                }
        }
        if (c + 1 < NC) sts_A(c + 1);  // writes other buffer; safe post-sync
    }

    const int er = lane >> 2, ec = (lane & 3) * 2;
#pragma unroll
    for (int i = 0; i < 2; i++) {
#pragma unroll
        for (int j = 0; j < 8; j++) {
            int row0 = rowBase + warp_m * 32 + i * 16 + er;
            int col = colBase + warp_n * 64 + j * 8 + ec;
            float2 v0 = make_float2(acc[i][j][0], acc[i][j][1]);
            float2 v1 = make_float2(acc[i][j][2], acc[i][j][3]);
            if (HAS_BIAS) {
                float2 bv = *(const float2*)(bias + col);
                v0.x += bv.x; v0.y += bv.y;
                v1.x += bv.x; v1.y += bv.y;
            }
            *(float2*)(C + (size_t)row0 * N + col) = v0;
            *(float2*)(C + (size_t)(row0 + 8) * N + col) = v1;
        }
    }
}

// ---------------------------------------------------------------------------
// fp32 SGEMM 64x64, dual-B (computes A*B1 and A*B2 in one launch).
// Grid x: [0, N/64) -> B1/C1, [N/64, 2*N/64) -> B2/C2.
// ---------------------------------------------------------------------------
__global__ __launch_bounds__(256) void sgemm64_dual(
    const float* __restrict__ A,
    const float* __restrict__ B1, const float* __restrict__ B2,
    float* __restrict__ C1, float* __restrict__ C2,
    int M, int N, int K)
{
    __shared__ float As[16][68];
    __shared__ float Bs[16][68];
    const int nb = N >> 6;
    const bool second = (int)blockIdx.x >= nb;
    const float* B = second ? B2 : B1;
    float* C = second ? C2 : C1;
    const int tid = threadIdx.x;
    const int rowBase = blockIdx.y * 64;
    const int colBase = (second ? blockIdx.x - nb : blockIdx.x) * 64;
    const int aRow = tid >> 2, aCol = (tid & 3) * 4;
    const int bRow = tid >> 4, bCol = (tid & 15) * 4;
    const int ty = tid >> 4, tx = tid & 15;

    float acc[4][4];
#pragma unroll
    for (int i = 0; i < 4; i++)
#pragma unroll
        for (int j = 0; j < 4; j++) acc[i][j] = 0.f;

    const bool aValid = (rowBase + aRow) < M;
    const float* Aptr = A + (size_t)(rowBase + aRow) * K + aCol;
    const float* Bptr = B + (size_t)bRow * N + colBase + bCol;

    for (int k0 = 0; k0 < K; k0 += 16) {
        float4 av = aValid ? *(const float4*)(Aptr + k0) : make_float4(0, 0, 0, 0);
        float4 bv = *(const float4*)(Bptr + (size_t)k0 * N);
        As[aCol + 0][aRow] = av.x; As[aCol + 1][aRow] = av.y;
        As[aCol + 2][aRow] = av.z; As[aCol + 3][aRow] = av.w;
        *(float4*)&Bs[bRow][bCol] = bv;
        __syncthreads();
#pragma unroll
        for (int kk = 0; kk < 16; kk++) {
            float a[4], b[4];
#pragma unroll
            for (int i = 0; i < 4; i++) a[i] = As[kk][ty * 4 + i];
#pragma unroll
            for (int j = 0; j < 4; j++) b[j] = Bs[kk][tx * 4 + j];
#pragma unroll
            for (int i = 0; i < 4; i++)
#pragma unroll
                for (int j = 0; j < 4; j++) acc[i][j] = fmaf(a[i], b[j], acc[i][j]);
        }
        __syncthreads();
    }
#pragma unroll
    for (int i = 0; i < 4; i++) {
        int rr = rowBase + ty * 4 + i;
        if (rr >= M) continue;
        *(float4*)(C + (size_t)rr * N + colBase + tx * 4) = *(float4*)acc[i];
    }
}

// ---------------------------------------------------------------------------
// Fused attention: qs merged into ws (each warp owns its 8 rows of both).
// smem = 77*68*2 + 64*80 floats = 62368 B -> 3 CTAs/SM.
// ---------------------------------------------------------------------------
__global__ __launch_bounds__(256) void attn_kernel(
    const float* __restrict__ qg, const float* __restrict__ kg,
    const float* __restrict__ vg, float* __restrict__ og)
{
    extern __shared__ float sm[];
    float* ks = sm;                  // 77 * 68
    float* vs = ks + GC * 68;        // 77 * 68
    float* qw = vs + GC * 68;        // 64 * 80 (q during scores, w after)

    const int n = blockIdx.z, h = blockIdx.y;
    const int qbase = blockIdx.x * 64;
    const int tid = threadIdx.x;
    const int warp = tid >> 5, lane = tid & 31;

    const float* kb = kg + (size_t)n * GC * GD + h * GS;
    const float* vb = vg + (size_t)n * GC * GD + h * GS;
    for (int i = tid; i < GC * GS; i += 256) {
        int c = i >> 6, s = i & 63;
        ks[c * 68 + s] = kb[(size_t)c * GD + s];
        vs[c * 68 + s] = vb[(size_t)c * GD + s];
    }
    const float* qb = qg + ((size_t)n * GQ + qbase) * GD + h * GS;
    for (int i = tid; i < 64 * 64; i += 256) {
        int r = i >> 6, s = i & 63;
        qw[r * 80 + s] = qb[(size_t)r * GD + s] * 0.125f;
    }
    __syncthreads();

    const int r0 = warp * 8;
    const bool c2ok = (lane < GC - 64);

    float sc0[8], sc1[8], sc2[8];
#pragma unroll
    for (int r = 0; r < 8; r++) { sc0[r] = 0.f; sc1[r] = 0.f; sc2[r] = 0.f; }
#pragma unroll
    for (int s = 0; s < 64; s += 4) {
        float4 k0 = *(const float4*)&ks[lane * 68 + s];
        float4 k1 = *(const float4*)&ks[(lane + 32) * 68 + s];
        float4 k2 = c2ok ? *(const float4*)&ks[(lane + 64) * 68 + s]
                         : make_float4(0.f, 0.f, 0.f, 0.f);
#pragma unroll
        for (int r = 0; r < 8; r++) {
            float4 qv = *(const float4*)&qw[(r0 + r) * 80 + s];
            sc0[r] = fmaf(qv.x, k0.x, fmaf(qv.y, k0.y, fmaf(qv.z, k0.z, fmaf(qv.w, k0.w, sc0[r]))));
            sc1[r] = fmaf(qv.x, k1.x, fmaf(qv.y, k1.y, fmaf(qv.z, k1.z, fmaf(qv.w, k1.w, sc1[r]))));
            sc2[r] = fmaf(qv.x, k2.x, fmaf(qv.y, k2.y, fmaf(qv.z, k2.z, fmaf(qv.w, k2.w, sc2[r]))));
        }
    }

    // softmax; overwrite this warp's q rows with weights (q is dead now)
#pragma unroll
    for (int r = 0; r < 8; r++) {
        float s2 = c2ok ? sc2[r] : -1e30f;
        float m = fmaxf(fmaxf(sc0[r], sc1[r]), s2);
#pragma unroll
        for (int o = 16; o; o >>= 1) m = fmaxf(m, __shfl_xor_sync(0xffffffffu, m, o));
        float e0 = __expf(sc0[r] - m);
        float e1 = __expf(sc1[r] - m);
        float e2 = c2ok ? __expf(s2 - m) : 0.f;
        float sum = e0 + e1 + e2;
#pragma unroll
        for (int o = 16; o; o >>= 1) sum += __shfl_xor_sync(0xffffffffu, sum, o);
        float inv = __frcp_rn(sum);
        qw[(r0 + r) * 80 + lane] = e0 * inv;
        qw[(r0 + r) * 80 + lane + 32] = e1 * inv;
        if (c2ok) qw[(r0 + r) * 80 + lane + 64] = e2 * inv;
    }
    __syncwarp();

    float a0[8], a1[8];
#pragma unroll
    for (int r = 0; r < 8; r++) { a0[r] = 0.f; a1[r] = 0.f; }
    int c = 0;
    for (; c + 4 <= GC; c += 4) {
        float v0[4], v1[4];
#pragma unroll
        for (int j = 0; j < 4; j++) {
            v0[j] = vs[(c + j) * 68 + lane];
            v1[j] = vs[(c + j) * 68 + lane + 32];
        }
#pragma unroll
        for (int r = 0; r < 8; r++) {
            float4 w = *(const float4*)&qw[(r0 + r) * 80 + c];
            a0[r] = fmaf(w.x, v0[0], fmaf(w.y, v0[1], fmaf(w.z, v0[2], fmaf(w.w, v0[3], a0[r]))));
            a1[r] = fmaf(w.x, v1[0], fmaf(w.y, v1[1], fmaf(w.z, v1[2], fmaf(w.w, v1[3], a1[r]))));
        }
    }
    for (; c < GC; c++) {
        float v0 = vs[c * 68 + lane], v1 = vs[c * 68 + lane + 32];
#pragma unroll
        for (int r = 0; r < 8; r++) {
            float w = qw[(r0 + r) * 80 + c];
            a0[r] = fmaf(w, v0, a0[r]);
            a1[r] = fmaf(w, v1, a1[r]);
        }
    }

    float* ob = og + ((size_t)n * GQ + qbase) * GD + h * GS;
#pragma unroll
    for (int r = 0; r < 8; r++) {
        ob[(size_t)(r0 + r) * GD + lane] = a0[r];
        ob[(size_t)(r0 + r) * GD + lane + 32] = a1[r];
    }
}

// ---------------------------------------------------------------------------
// W[K][N] fp32 -> Wt[N][K] hi/lo bf16
__global__ void transpose_split(const float* __restrict__ W,
                                __nv_bfloat16* __restrict__ Whi,
                                __nv_bfloat16* __restrict__ Wlo, int K, int N)
{
    __shared__ float t[32][33];
    int k0 = blockIdx.y * 32, n0 = blockIdx.x * 32;
    int x = threadIdx.x, y = threadIdx.y;  // 32 x 8
#pragma unroll
    for (int i = 0; i < 32; i += 8) t[y + i][x] = W[(size_t)(k0 + y + i) * N + n0 + x];
    __syncthreads();
#pragma unroll
    for (int i = 0; i < 32; i += 8) {
        __nv_bfloat16 h, l;
        split_bf16(t[x][y + i], h, l);
        Whi[(size_t)(n0 + y + i) * K + k0 + x] = h;
        Wlo[(size_t)(n0 + y + i) * K + k0 + x] = l;
    }
}

// ---------------------------------------------------------------------------
extern "C" void kernel_launch(void* const* d_in, const int* in_sizes, int n_in,
                              void* d_out, int out_size)
{
    const float* query   = (const float*)d_in[0];
    const float* context = (const float*)d_in[1];
    const float* Wq      = (const float*)d_in[2];
    const float* Wk      = (const float*)d_in[3];
    const float* Wv      = (const float*)d_in[4];
    const float* Wo      = (const float*)d_in[5];
    const float* bo      = (const float*)d_in[6];
    float* out = (float*)d_out;

    void *pq, *pa, *pk, *pv, *pwqh, *pwql, *pwoh, *pwol;
    cudaGetSymbolAddress(&pq, g_q);
    cudaGetSymbolAddress(&pa, g_att);
    cudaGetSymbolAddress(&pk, g_k);
    cudaGetSymbolAddress(&pv, g_v);
    cudaGetSymbolAddress(&pwqh, g_wqT_hi);
    cudaGetSymbolAddress(&pwql, g_wqT_lo);
    cudaGetSymbolAddress(&pwoh, g_woT_hi);
    cudaGetSymbolAddress(&pwol, g_woT_lo);

    cudaFuncSetAttribute(gemm_mma3f<false>, cudaFuncAttributeMaxDynamicSharedMemorySize, GEMM_SMEM);
    cudaFuncSetAttribute(gemm_mma3f<true>,  cudaFuncAttributeMaxDynamicSharedMemorySize, GEMM_SMEM);

    // prep: W transposes -> hi/lo (tiny)
    {
        dim3 b(32, 8);
        transpose_split<<<dim3(GD / 32, GD / 32), b>>>(Wq, (__nv_bfloat16*)pwqh,
                                                       (__nv_bfloat16*)pwql, GD, GD);
        transpose_split<<<dim3(GD / 32, GD / 32), b>>>(Wo, (__nv_bfloat16*)pwoh,
                                                       (__nv_bfloat16*)pwol, GD, GD);
    }
    // K+V projections fused (320 blocks)
    {
        dim3 grid((GD / 64) * 2, (GN * GC + 63) / 64);
        sgemm64_dual<<<grid, 256>>>(context, Wk, Wv, (float*)pk, (float*)pv,
                                    GN * GC, GD, GDC);
    }
    // Q projection (bf16x3 tensor cores, pipelined fp32 A)
    {
        dim3 grid(GD / 128, GM / 128);
        gemm_mma3f<false><<<grid, 256, GEMM_SMEM>>>(
            query, (const __nv_bfloat16*)pwqh, (const __nv_bfloat16*)pwql,
            nullptr, (float*)pq, GM, GD, GD);
    }
    // attention
    {
        int smem = (GC * 68 * 2 + 64 * 80) * (int)sizeof(float);
        cudaFuncSetAttribute(attn_kernel, cudaFuncAttributeMaxDynamicSharedMemorySize, smem);
        dim3 grid(GQ / 64, GH, GN);
        attn_kernel<<<grid, 256, smem>>>((const float*)pq, (const float*)pk,
                                         (const float*)pv, (float*)pa);
    }
    // O projection + bias
    {
        dim3 grid(GD / 128, GM / 128);
        gemm_mma3f<true><<<grid, 256, GEMM_SMEM>>>(
            (const float*)pa, (const __nv_bfloat16*)pwoh, (const __nv_bfloat16*)pwol,
            bo, out, GM, GD, GD);
    }
}